// round 3
// baseline (speedup 1.0000x reference)
#include <cuda_runtime.h>
#include <math.h>

#define NB   4096
#define ND   4096
#define NCLS 10
#define NCHUNK 32
#define RPC  (NB / NCHUNK)   // 128 rows per chunk

// Scratch (no allocations allowed -> __device__ globals)
__device__ float  g_r[NB];
__device__ int    g_cls[NB];
__device__ double g_tc[NCLS];
__device__ int    g_nc[NCLS];
__device__ double g_ce;
__device__ double g_s2;
__device__ float  g_part[NCHUNK][NCLS][ND];   // ~5.24 MB partial class column sums

// ---------------------------------------------------------------- zero accums
__global__ void k_zero() {
    int t = threadIdx.x;
    if (t < NCLS) { g_tc[t] = 0.0; g_nc[t] = 0; }
    if (t == 0)   { g_ce = 0.0; g_s2 = 0.0; }
}

// ------------------------------------------------- per-row stats + CE + argmax
// One block per row (4096 blocks x 128 threads). Streams grad once (64 MB).
__global__ void __launch_bounds__(128) k_rowstats(
    const float* __restrict__ grad, const float* __restrict__ outputs,
    const int* __restrict__ y) {
    int row = blockIdx.x;
    int tid = threadIdx.x;
    const float4* gp = (const float4*)grad + (size_t)row * (ND / 4);

    float mn = 3.0e38f, sum = 0.f, sq = 0.f;
#pragma unroll
    for (int j = 0; j < 8; j++) {
        float4 v = gp[j * 128 + tid];
        mn  = fminf(mn, fminf(fminf(v.x, v.y), fminf(v.z, v.w)));
        sum += (v.x + v.y) + (v.z + v.w);
        sq  += (v.x * v.x + v.y * v.y) + (v.z * v.z + v.w * v.w);
    }
#pragma unroll
    for (int o = 16; o; o >>= 1) {
        mn   = fminf(mn, __shfl_xor_sync(0xffffffffu, mn, o));
        sum += __shfl_xor_sync(0xffffffffu, sum, o);
        sq  += __shfl_xor_sync(0xffffffffu, sq, o);
    }
    __shared__ float smn[4], ssum[4], ssq[4];
    int w = tid >> 5;
    if ((tid & 31) == 0) { smn[w] = mn; ssum[w] = sum; ssq[w] = sq; }
    __syncthreads();
    if (tid == 0) {
        mn = fminf(fminf(smn[0], smn[1]), fminf(smn[2], smn[3]));
        double s = (double)ssum[0] + ssum[1] + ssum[2] + ssum[3];
        double q = (double)ssq[0] + ssq[1] + ssq[2] + ssq[3];
        double mnd = (double)mn;
        // sum of (g - min)^2 over the row; (max-min) scaling cancels in cosine
        double var = q - 2.0 * mnd * s + (double)ND * mnd * mnd;
        float r = (float)(1.0 / sqrt(var));
        g_r[row] = r;

        // outputs row: argmax (first max, matching jnp.argmax) + log-softmax CE
        const float* o = outputs + row * NCLS;
        float mx = o[0]; int am = 0;
#pragma unroll
        for (int c = 1; c < NCLS; c++) { float v = o[c]; if (v > mx) { mx = v; am = c; } }
        double e = 0.0;
#pragma unroll
        for (int c = 0; c < NCLS; c++) e += exp((double)o[c] - (double)mx);
        double lse = (double)mx + log(e);
        atomicAdd(&g_ce, lse - (double)o[y[row]]);
        g_cls[row] = am;
        atomicAdd(&g_tc[am], mnd * (double)r);
        atomicAdd(&g_nc[am], 1);
    }
}

// ------------------------------------- class-weighted column sums A = W @ grad
// grid (4, 32): blockIdx.x selects 1024-column stripe, blockIdx.y selects a
// 128-row chunk. Each thread owns 4 columns (float4) with 10 class accumulators
// in registers; writes its chunk-partial to g_part (no atomics on the hot path).
__global__ void __launch_bounds__(256) k_classsum(const float* __restrict__ grad) {
    int col  = blockIdx.x * 1024 + threadIdx.x * 4;
    int row0 = blockIdx.y * RPC;
    __shared__ float sh_r[RPC];
    __shared__ int   sh_c[RPC];
    if (threadIdx.x < RPC) {
        sh_r[threadIdx.x] = g_r[row0 + threadIdx.x];
        sh_c[threadIdx.x] = g_cls[row0 + threadIdx.x];
    }
    __syncthreads();

    float4 acc[NCLS];
#pragma unroll
    for (int k = 0; k < NCLS; k++) acc[k] = make_float4(0.f, 0.f, 0.f, 0.f);

    const float* base = grad + (size_t)row0 * ND + col;
    for (int i = 0; i < RPC; i++) {
        float4 v = *(const float4*)(base + (size_t)i * ND);
        int c = sh_c[i];
        float r = sh_r[i];
#pragma unroll
        for (int k = 0; k < NCLS; k++) {
            float m = (c == k) ? r : 0.0f;
            acc[k].x = fmaf(m, v.x, acc[k].x);
            acc[k].y = fmaf(m, v.y, acc[k].y);
            acc[k].z = fmaf(m, v.z, acc[k].z);
            acc[k].w = fmaf(m, v.w, acc[k].w);
        }
    }
#pragma unroll
    for (int k = 0; k < NCLS; k++)
        *(float4*)&g_part[blockIdx.y][k][col] = acc[k];
}

// ------------------------------------------ ||S_c||^2 with mean-shift (t_c)
// grid (10, 8): class c, column segment seg (512 cols each).
__global__ void __launch_bounds__(256) k_norm2() {
    int c   = blockIdx.x;
    int seg = blockIdx.y;
    double tc = g_tc[c];
    double local = 0.0;
    for (int d = seg * 512 + threadIdx.x; d < (seg + 1) * 512; d += 256) {
        float s = 0.f;
#pragma unroll
        for (int ch = 0; ch < NCHUNK; ch++) s += g_part[ch][c][d];
        double v = (double)s - tc;
        local += v * v;
    }
#pragma unroll
    for (int o = 16; o; o >>= 1)
        local += __shfl_xor_sync(0xffffffffu, local, o);
    __shared__ double sd[8];
    if ((threadIdx.x & 31) == 0) sd[threadIdx.x >> 5] = local;
    __syncthreads();
    if (threadIdx.x == 0) {
        double t = 0.0;
        for (int i = 0; i < 8; i++) t += sd[i];
        atomicAdd(&g_s2, t);
    }
}

// ------------------------------------------------------------ final scalar
__global__ void k_final(float* __restrict__ out) {
    double P = 0.0;
    for (int c = 0; c < NCLS; c++)
        P += 0.5 * (double)g_nc[c] * (double)(g_nc[c] - 1);
    double simsum = 0.5 * (g_s2 - (double)NB);   // sum of sim over i<j same-class
    double xloss  = (P - simsum) / (double)NB;
    double ce     = g_ce / (double)NB;
    out[0] = (float)(ce + xloss);
}

extern "C" void kernel_launch(void* const* d_in, const int* in_sizes, int n_in,
                              void* d_out, int out_size) {
    (void)out_size;
    const float* outputs = nullptr;
    const float* grad    = nullptr;
    const int*   y       = nullptr;
    for (int i = 0; i < n_in; i++) {
        if      (in_sizes[i] == NB * ND)   grad    = (const float*)d_in[i];
        else if (in_sizes[i] == NB * NCLS) outputs = (const float*)d_in[i];
        else if (in_sizes[i] == NB)        y       = (const int*)d_in[i];
    }
    float* out = (float*)d_out;

    k_zero<<<1, 32>>>();
    k_rowstats<<<NB, 128>>>(grad, outputs, y);
    k_classsum<<<dim3(4, NCHUNK), 256>>>(grad);
    k_norm2<<<dim3(NCLS, 8), 256>>>();
    k_final<<<1, 1>>>(out);
}

// round 5
// speedup vs baseline: 2.9099x; 2.9099x over previous
#include <cuda_runtime.h>
#include <math.h>

#define NB    4096
#define ND    4096
#define NCLS  10
#define NSUB  8            // sub-chunks per class in the sorted pass
#define MAXLEN 512         // ceil(NB / NSUB) upper bound on rows per sub-chunk

// Scratch (no allocations allowed -> __device__ globals)
__device__ float  g_r[NB];          // 1/||g_i - min_i||
__device__ float  g_mn[NB];         // row min
__device__ int    g_cls[NB];        // argmax class
__device__ int    g_pos[NB];        // within-class arrival index
__device__ int    g_order[NB];      // rows sorted by class
__device__ float  g_rs[NB];         // r gathered into sorted order
__device__ int    g_off[NCLS + 1];  // class offsets (prefix of counts)
__device__ int    g_nc[NCLS];
__device__ double g_tc[NCLS];       // sum over class of mn_i * r_i
__device__ double g_ce;
__device__ double g_s2;
__device__ float  g_part[NCLS][NSUB][ND];  // per-(class,sub) column partials, 1.31 MB

// ---------------------------------------------------------------- zero accums
__global__ void k_zero() {
    int t = threadIdx.x;
    if (t < NCLS) { g_tc[t] = 0.0; g_nc[t] = 0; }
    if (t == 0)   { g_ce = 0.0; g_s2 = 0.0; }
}

// --------------------------------------- CE + argmax + class counts/positions
// One thread per row. float log-sum-exp (CE ~2.4 of ~2.6 total; fp32 is ample).
__global__ void __launch_bounds__(256) k_ce(
    const float* __restrict__ outputs, const int* __restrict__ y) {
    int row = blockIdx.x * 256 + threadIdx.x;
    const float* o = outputs + row * NCLS;
    float v0 = o[0];
    float mx = v0; int am = 0;
    float vals[NCLS];
    vals[0] = v0;
#pragma unroll
    for (int c = 1; c < NCLS; c++) {
        float v = o[c]; vals[c] = v;
        if (v > mx) { mx = v; am = c; }   // strict > == first max (jnp.argmax)
    }
    float e = 0.f;
#pragma unroll
    for (int c = 0; c < NCLS; c++) e += __expf(vals[c] - mx);
    double local = (double)mx + log((double)e) - (double)vals[y[row]];

    g_cls[row] = am;
    g_pos[row] = atomicAdd(&g_nc[am], 1);

#pragma unroll
    for (int off = 16; off; off >>= 1)
        local += __shfl_xor_sync(0xffffffffu, local, off);
    if ((threadIdx.x & 31) == 0) atomicAdd(&g_ce, local);
}

// ------------------------------------------------- per-row min / sum / sumsq
// One block per row (4096 blocks x 128 threads). Streams grad once (64 MB).
__global__ void __launch_bounds__(128) k_rowstats(const float* __restrict__ grad) {
    int row = blockIdx.x;
    int tid = threadIdx.x;
    const float4* gp = (const float4*)grad + (size_t)row * (ND / 4);

    float mn = 3.0e38f, sum = 0.f, sq = 0.f;
#pragma unroll
    for (int j = 0; j < 8; j++) {
        float4 v = gp[j * 128 + tid];
        mn  = fminf(mn, fminf(fminf(v.x, v.y), fminf(v.z, v.w)));
        sum += (v.x + v.y) + (v.z + v.w);
        sq  += (v.x * v.x + v.y * v.y) + (v.z * v.z + v.w * v.w);
    }
#pragma unroll
    for (int o = 16; o; o >>= 1) {
        mn   = fminf(mn, __shfl_xor_sync(0xffffffffu, mn, o));
        sum += __shfl_xor_sync(0xffffffffu, sum, o);
        sq  += __shfl_xor_sync(0xffffffffu, sq, o);
    }
    __shared__ float smn[4], ssum[4], ssq[4];
    int w = tid >> 5;
    if ((tid & 31) == 0) { smn[w] = mn; ssum[w] = sum; ssq[w] = sq; }
    __syncthreads();
    if (tid == 0) {
        mn = fminf(fminf(smn[0], smn[1]), fminf(smn[2], smn[3]));
        double s = (double)ssum[0] + ssum[1] + ssum[2] + ssum[3];
        double q = (double)ssq[0] + ssq[1] + ssq[2] + ssq[3];
        double mnd = (double)mn;
        // sum of (g - min)^2 ; the (max-min) scale cancels in cosine similarity
        double var = q - 2.0 * mnd * s + (double)ND * mnd * mnd;
        g_r[row]  = (float)(1.0 / sqrt(var));
        g_mn[row] = mn;
    }
}

// ------------------------------------------------------ 10-entry prefix sum
__global__ void k_offsets() {
    if (threadIdx.x == 0) {
        int acc = 0;
        g_off[0] = 0;
        for (int c = 0; c < NCLS; c++) { acc += g_nc[c]; g_off[c + 1] = acc; }
    }
}

// ---------------------------------- scatter rows into class-sorted order + t_c
__global__ void __launch_bounds__(256) k_scatter() {
    int row = blockIdx.x * 256 + threadIdx.x;
    int c = g_cls[row];
    int p = g_off[c] + g_pos[row];
    float r = g_r[row];
    g_order[p] = row;
    g_rs[p]    = r;
    atomicAdd(&g_tc[c], (double)g_mn[row] * (double)r);
}

// ---------------------------- class column sums over class-sorted rows
// grid (4 stripes, NCLS, NSUB). One class per block -> 1 FFMA per element.
__global__ void __launch_bounds__(256) k_classsum(const float* __restrict__ grad) {
    int col = blockIdx.x * 1024 + threadIdx.x * 4;
    int c   = blockIdx.y;
    int s   = blockIdx.z;
    int beg = g_off[c], end = g_off[c + 1];
    int n   = end - beg;
    int len = (n + NSUB - 1) / NSUB;
    int lo  = beg + s * len;
    int hi  = min(lo + len, end);
    int cnt = max(hi - lo, 0);

    __shared__ int   sidx[MAXLEN];
    __shared__ float sr[MAXLEN];
    for (int i = threadIdx.x; i < cnt; i += 256) {
        sidx[i] = g_order[lo + i];
        sr[i]   = g_rs[lo + i];
    }
    __syncthreads();

    float4 acc = make_float4(0.f, 0.f, 0.f, 0.f);
    int i = 0;
    for (; i + 4 <= cnt; i += 4) {
        const float4 v0 = *(const float4*)(grad + (size_t)sidx[i + 0] * ND + col);
        const float4 v1 = *(const float4*)(grad + (size_t)sidx[i + 1] * ND + col);
        const float4 v2 = *(const float4*)(grad + (size_t)sidx[i + 2] * ND + col);
        const float4 v3 = *(const float4*)(grad + (size_t)sidx[i + 3] * ND + col);
        float r0 = sr[i + 0], r1 = sr[i + 1], r2 = sr[i + 2], r3 = sr[i + 3];
        acc.x = fmaf(r0, v0.x, acc.x); acc.y = fmaf(r0, v0.y, acc.y);
        acc.z = fmaf(r0, v0.z, acc.z); acc.w = fmaf(r0, v0.w, acc.w);
        acc.x = fmaf(r1, v1.x, acc.x); acc.y = fmaf(r1, v1.y, acc.y);
        acc.z = fmaf(r1, v1.z, acc.z); acc.w = fmaf(r1, v1.w, acc.w);
        acc.x = fmaf(r2, v2.x, acc.x); acc.y = fmaf(r2, v2.y, acc.y);
        acc.z = fmaf(r2, v2.z, acc.z); acc.w = fmaf(r2, v2.w, acc.w);
        acc.x = fmaf(r3, v3.x, acc.x); acc.y = fmaf(r3, v3.y, acc.y);
        acc.z = fmaf(r3, v3.z, acc.z); acc.w = fmaf(r3, v3.w, acc.w);
    }
    for (; i < cnt; i++) {
        const float4 v = *(const float4*)(grad + (size_t)sidx[i] * ND + col);
        float r = sr[i];
        acc.x = fmaf(r, v.x, acc.x); acc.y = fmaf(r, v.y, acc.y);
        acc.z = fmaf(r, v.z, acc.z); acc.w = fmaf(r, v.w, acc.w);
    }
    // unconditional write covers empty classes/subs (no pre-zeroing needed)
    *(float4*)&g_part[c][s][col] = acc;
}

// ------------------------------------------ ||S_c||^2 with mean-shift (t_c)
// grid (NCLS, 4): class c, 1024-column segment. Thread owns 4 columns.
__global__ void __launch_bounds__(256) k_norm2() {
    int c   = blockIdx.x;
    int col = blockIdx.y * 1024 + threadIdx.x * 4;
    double tc = g_tc[c];
    float4 s = make_float4(0.f, 0.f, 0.f, 0.f);
#pragma unroll
    for (int sub = 0; sub < NSUB; sub++) {
        float4 v = *(const float4*)&g_part[c][sub][col];
        s.x += v.x; s.y += v.y; s.z += v.z; s.w += v.w;
    }
    double a = (double)s.x - tc, b = (double)s.y - tc;
    double d = (double)s.z - tc, e = (double)s.w - tc;
    double local = a * a + b * b + d * d + e * e;
#pragma unroll
    for (int o = 16; o; o >>= 1)
        local += __shfl_xor_sync(0xffffffffu, local, o);
    __shared__ double sd[8];
    if ((threadIdx.x & 31) == 0) sd[threadIdx.x >> 5] = local;
    __syncthreads();
    if (threadIdx.x == 0) {
        double t = 0.0;
        for (int i = 0; i < 8; i++) t += sd[i];
        atomicAdd(&g_s2, t);
    }
}

// ------------------------------------------------------------ final scalar
__global__ void k_final(float* __restrict__ out) {
    double P = 0.0;
    for (int c = 0; c < NCLS; c++)
        P += 0.5 * (double)g_nc[c] * (double)(g_nc[c] - 1);
    double simsum = 0.5 * (g_s2 - (double)NB);   // sum of sim over i<j same-class
    double xloss  = (P - simsum) / (double)NB;
    double ce     = g_ce / (double)NB;
    out[0] = (float)(ce + xloss);
}

extern "C" void kernel_launch(void* const* d_in, const int* in_sizes, int n_in,
                              void* d_out, int out_size) {
    (void)out_size;
    const float* outputs = nullptr;
    const float* grad    = nullptr;
    const int*   y       = nullptr;
    for (int i = 0; i < n_in; i++) {
        if      (in_sizes[i] == NB * ND)   grad    = (const float*)d_in[i];
        else if (in_sizes[i] == NB * NCLS) outputs = (const float*)d_in[i];
        else if (in_sizes[i] == NB)        y       = (const int*)d_in[i];
    }
    float* out = (float*)d_out;

    k_zero<<<1, 32>>>();
    k_ce<<<NB / 256, 256>>>(outputs, y);
    k_rowstats<<<NB, 128>>>(grad);
    k_offsets<<<1, 32>>>();
    k_scatter<<<NB / 256, 256>>>();
    k_classsum<<<dim3(4, NCLS, NSUB), 256>>>(grad);
    k_norm2<<<dim3(NCLS, 4), 256>>>();
    k_final<<<1, 1>>>(out);
}